// round 2
// baseline (speedup 1.0000x reference)
#include <cuda_runtime.h>
#include <cstdint>

// ---------------------------------------------------------------------------
// EdgeDecoder restructure:
//   A[n] = z[n] @ W1[0:128, :]     (128 cols)
//   B[n] = z[n] @ W1[128:256, :]   (128 cols)
//   score[e] = relu(A[src] + B[dst] + b1) . W2 + b2
//
// Kernel 0: probe edge_index dtype (int32 vs int64) on device.
// Kernel 1: fp32 GEMM  [N,128] @ [128,256] -> g_AB[n][0:128]=A, [128:256]=B
//           using packed fma.rn.f32x2 (Blackwell 2x fp32 rate).
// Kernel 2: per-edge gather+relu+dot, one warp per edge. AB table (102.4MB)
//           is L2-resident -> L2-bandwidth bound.
// ---------------------------------------------------------------------------

#define HID 128
#define N_MAX 100000

__device__ float g_AB[(size_t)N_MAX * 256];
__device__ int   g_is64;

typedef unsigned long long u64;

__device__ __forceinline__ u64 packf2(float lo, float hi) {
    u64 r;
    asm("mov.b64 %0, {%1, %2};" : "=l"(r) : "f"(lo), "f"(hi));
    return r;
}

__device__ __forceinline__ void unpackf2(u64 v, float& lo, float& hi) {
    asm("mov.b64 {%0, %1}, %2;" : "=f"(lo), "=f"(hi) : "l"(v));
}

__device__ __forceinline__ void fma2(u64& acc, u64 a, u64 b) {
    asm("fma.rn.f32x2 %0, %1, %2, %0;" : "+l"(acc) : "l"(a), "l"(b));
}

// ---------------------------------------------------------------------------
// Kernel 0: dtype probe. If edge_index is int64 (little-endian) holding values
// < 2^31, then int32-view odd positions (high words) are all zero. For an
// int32 layout those positions hold random node indices — 8 zeros in a row
// has probability ~1e-40. Deterministic: same input -> same flag.
// ---------------------------------------------------------------------------
__global__ void detect_idx_dtype(const int* __restrict__ ei32) {
    int all0 = 1;
#pragma unroll
    for (int i = 0; i < 8; ++i)
        all0 &= (ei32[2 * i + 1] == 0);
    g_is64 = all0;
}

// ---------------------------------------------------------------------------
// GEMM: tile 64 rows x 256 cols per block, 256 threads.
// Thread (tx = t&31, ty = t>>5) computes rows ty*8..+7,
// cols {tx*4..tx*4+3} (A half) and {128+tx*4..+3} (B half).
// ---------------------------------------------------------------------------
__global__ __launch_bounds__(256, 2) void precompute_gemm(
    const float* __restrict__ z,   // [N, 128]
    const float* __restrict__ W1,  // [256, 128]
    int N)
{
    __shared__ __align__(16) float Zs[64][20];   // 64 rows x 16 K-chunk, pad to 20
    __shared__ __align__(16) float Ws[16][256];  // 16 K x 256 cols

    const int t  = threadIdx.x;
    const int tx = t & 31;
    const int ty = t >> 5;
    const int row0 = blockIdx.x * 64;

    u64 acc0[8][2], acc1[8][2];
    u64 z2 = packf2(0.f, 0.f);
#pragma unroll
    for (int i = 0; i < 8; ++i) {
        acc0[i][0] = z2; acc0[i][1] = z2;
        acc1[i][0] = z2; acc1[i][1] = z2;
    }

    for (int k0 = 0; k0 < 128; k0 += 16) {
        // ---- load Z tile: 64x16 floats, 4 per thread (float4) ----
        {
            int idx = t * 4;           // 0..1020
            int r   = idx >> 4;        // 0..63
            int kk  = idx & 15;        // {0,4,8,12}
            int gr  = row0 + r;
            if (gr >= N) gr = N - 1;   // clamp (discarded at store)
            float4 v = *(const float4*)(z + (size_t)gr * HID + k0 + kk);
            *(float4*)&Zs[r][kk] = v;
        }
        // ---- load W tile: 16x256 floats, 16 per thread ----
#pragma unroll
        for (int m = 0; m < 4; ++m) {
            int idx = m * 1024 + t * 4;    // 0..4092
            int kk  = idx >> 8;            // 0..15
            int j   = idx & 255;           // 0..252 step 4
            const float* src = (j < 128)
                ? (W1 + (size_t)(k0 + kk) * HID + j)                // A half
                : (W1 + (size_t)(128 + k0 + kk) * HID + (j - 128)); // B half
            *(float4*)&Ws[kk][j] = *(const float4*)src;
        }
        __syncthreads();

        // ---- compute ----
#pragma unroll
        for (int kq = 0; kq < 4; ++kq) {
            float zr[8][4];
#pragma unroll
            for (int i = 0; i < 8; ++i) {
                float4 v = *(const float4*)&Zs[ty * 8 + i][kq * 4];
                zr[i][0] = v.x; zr[i][1] = v.y; zr[i][2] = v.z; zr[i][3] = v.w;
            }
#pragma unroll
            for (int kk = 0; kk < 4; ++kk) {
                const int krow = kq * 4 + kk;
                float4 w0 = *(const float4*)&Ws[krow][tx * 4];
                float4 w1 = *(const float4*)&Ws[krow][128 + tx * 4];
                u64 w0a = packf2(w0.x, w0.y), w0b = packf2(w0.z, w0.w);
                u64 w1a = packf2(w1.x, w1.y), w1b = packf2(w1.z, w1.w);
#pragma unroll
                for (int i = 0; i < 8; ++i) {
                    u64 zz = packf2(zr[i][kk], zr[i][kk]);
                    fma2(acc0[i][0], zz, w0a);
                    fma2(acc0[i][1], zz, w0b);
                    fma2(acc1[i][0], zz, w1a);
                    fma2(acc1[i][1], zz, w1b);
                }
            }
        }
        __syncthreads();
    }

    // ---- store ----
#pragma unroll
    for (int i = 0; i < 8; ++i) {
        int row = row0 + ty * 8 + i;
        if (row < N) {
            float4 o0, o1;
            unpackf2(acc0[i][0], o0.x, o0.y);
            unpackf2(acc0[i][1], o0.z, o0.w);
            unpackf2(acc1[i][0], o1.x, o1.y);
            unpackf2(acc1[i][1], o1.z, o1.w);
            *(float4*)&g_AB[(size_t)row * 256 + tx * 4]       = o0;
            *(float4*)&g_AB[(size_t)row * 256 + 128 + tx * 4] = o1;
        }
    }
}

// ---------------------------------------------------------------------------
// Edge kernel: one warp per edge. Lane l owns channels 4l..4l+3.
// score[e] = sum_c relu(A[src][c] + B[dst][c] + b1[c]) * W2[c] + b2
// ---------------------------------------------------------------------------
__global__ __launch_bounds__(256) void edge_score(
    const void* __restrict__ ei_raw,   // [2, E] int32 or int64 (see g_is64)
    const float* __restrict__ b1,      // [128]
    const float* __restrict__ W2,      // [128]
    const float* __restrict__ b2,      // [1]
    float* __restrict__ out,           // [E]
    int E, int N)
{
    const int lane = threadIdx.x & 31;
    const int e = blockIdx.x * (blockDim.x >> 5) + (threadIdx.x >> 5);
    if (e >= E) return;

    const float4 bb = *(const float4*)(b1 + lane * 4);
    const float4 ww = *(const float4*)(W2 + lane * 4);

    unsigned s, d;
    if (g_is64) {
        const long long* ei = (const long long*)ei_raw;
        s = (unsigned)ei[e];
        d = (unsigned)ei[(size_t)E + e];
    } else {
        const int* ei = (const int*)ei_raw;
        s = (unsigned)ei[e];
        d = (unsigned)ei[(size_t)E + e];
    }
    // defensive clamp: bad contract -> wrong answer (measurable), not a crash
    s = min(s, (unsigned)(N - 1));
    d = min(d, (unsigned)(N - 1));

    const float4 a  = *(const float4*)(g_AB + (size_t)s * 256 + lane * 4);
    const float4 bv = *(const float4*)(g_AB + (size_t)d * 256 + 128 + lane * 4);

    float h0 = fmaxf(a.x + bv.x + bb.x, 0.f);
    float h1 = fmaxf(a.y + bv.y + bb.y, 0.f);
    float h2 = fmaxf(a.z + bv.z + bb.z, 0.f);
    float h3 = fmaxf(a.w + bv.w + bb.w, 0.f);

    float sum = h0 * ww.x + h1 * ww.y + h2 * ww.z + h3 * ww.w;

#pragma unroll
    for (int off = 16; off; off >>= 1)
        sum += __shfl_xor_sync(0xFFFFFFFFu, sum, off);

    if (lane == 0)
        out[e] = sum + __ldg(b2);
}

// ---------------------------------------------------------------------------
extern "C" void kernel_launch(void* const* d_in, const int* in_sizes, int n_in,
                              void* d_out, int out_size)
{
    const float* z   = (const float*)d_in[0];
    const void*  ei  = d_in[1];               // edge_index [2,E], dtype probed
    const float* W1  = (const float*)d_in[2];
    const float* b1  = (const float*)d_in[3];
    const float* W2  = (const float*)d_in[4];
    const float* b2  = (const float*)d_in[5];
    float*       out = (float*)d_out;

    const int N = in_sizes[0] / HID;   // 100000
    const int E = in_sizes[1] / 2;     // 1600000

    detect_idx_dtype<<<1, 1>>>((const int*)ei);

    precompute_gemm<<<(N + 63) / 64, 256>>>(z, W1, N);

    const int warps_per_block = 8;
    edge_score<<<(E + warps_per_block - 1) / warps_per_block, 256>>>(
        ei, b1, W2, b2, out, E, N);
}

// round 3
// speedup vs baseline: 1.3419x; 1.3419x over previous
#include <cuda_runtime.h>
#include <cuda_fp16.h>
#include <cstdint>

// ---------------------------------------------------------------------------
// EdgeDecoder restructure:
//   A[n] = z[n] @ W1[0:128, :]     (128 cols)
//   B[n] = z[n] @ W1[128:256, :]   (128 cols)
//   score[e] = relu(A[src] + B[dst] + b1) . W2 + b2
//
// Kernel 1: fp32 GEMM (packed fma.rn.f32x2) -> g_AB in fp16
//           (node row: 512B = 128 A halves | 128 B halves).
//           Block 0 also probes edge_index dtype (int32 vs int64).
// Kernel 2: per-edge gather+relu+dot. 16 lanes per edge (2 edges/warp),
//           lane owns 8 channels = one 16B load per half. AB table (51MB)
//           L2-resident -> ~820MB of L2 gathers total.
// ---------------------------------------------------------------------------

#define HID 128
#define N_MAX 100000

__device__ __align__(16) __half g_AB[(size_t)N_MAX * 256];
__device__ int g_is64;

typedef unsigned long long u64;

__device__ __forceinline__ u64 packf2(float lo, float hi) {
    u64 r;
    asm("mov.b64 %0, {%1, %2};" : "=l"(r) : "f"(lo), "f"(hi));
    return r;
}
__device__ __forceinline__ void unpackf2(u64 v, float& lo, float& hi) {
    asm("mov.b64 {%0, %1}, %2;" : "=f"(lo), "=f"(hi) : "l"(v));
}
__device__ __forceinline__ void fma2(u64& acc, u64 a, u64 b) {
    asm("fma.rn.f32x2 %0, %1, %2, %0;" : "+l"(acc) : "l"(a), "l"(b));
}

// ---------------------------------------------------------------------------
// GEMM: 64 rows x 256 cols per block, 256 threads.
// Thread (tx,ty) computes rows ty*8..+7, cols {tx*4..+3} (A) and {128+tx*4..+3} (B).
// ---------------------------------------------------------------------------
__global__ __launch_bounds__(256, 2) void precompute_gemm(
    const float* __restrict__ z,    // [N, 128]
    const float* __restrict__ W1,   // [256, 128]
    const int*   __restrict__ ei32, // edge_index viewed as int32 (for probe)
    int N)
{
    // dtype probe: int64 little-endian with values < 2^31 has zero high words
    // at odd int32 positions. 8 consecutive zeros is impossible for int32
    // layout of random indices (p ~ 1e-40). Consumed only by the NEXT kernel.
    if (blockIdx.x == 0 && threadIdx.x == 0) {
        int all0 = 1;
#pragma unroll
        for (int i = 0; i < 8; ++i)
            all0 &= (ei32[2 * i + 1] == 0);
        g_is64 = all0;
    }

    __shared__ __align__(16) float Zs[64][20];
    __shared__ __align__(16) float Ws[16][256];

    const int t  = threadIdx.x;
    const int tx = t & 31;
    const int ty = t >> 5;
    const int row0 = blockIdx.x * 64;

    u64 acc0[8][2], acc1[8][2];
    u64 z2 = packf2(0.f, 0.f);
#pragma unroll
    for (int i = 0; i < 8; ++i) {
        acc0[i][0] = z2; acc0[i][1] = z2;
        acc1[i][0] = z2; acc1[i][1] = z2;
    }

    for (int k0 = 0; k0 < 128; k0 += 16) {
        {
            int idx = t * 4;
            int r   = idx >> 4;
            int kk  = idx & 15;
            int gr  = row0 + r;
            if (gr >= N) gr = N - 1;
            float4 v = *(const float4*)(z + (size_t)gr * HID + k0 + kk);
            *(float4*)&Zs[r][kk] = v;
        }
#pragma unroll
        for (int m = 0; m < 4; ++m) {
            int idx = m * 1024 + t * 4;
            int kk  = idx >> 8;
            int j   = idx & 255;
            const float* src = (j < 128)
                ? (W1 + (size_t)(k0 + kk) * HID + j)
                : (W1 + (size_t)(128 + k0 + kk) * HID + (j - 128));
            *(float4*)&Ws[kk][j] = *(const float4*)src;
        }
        __syncthreads();

#pragma unroll
        for (int kq = 0; kq < 4; ++kq) {
            float zr[8][4];
#pragma unroll
            for (int i = 0; i < 8; ++i) {
                float4 v = *(const float4*)&Zs[ty * 8 + i][kq * 4];
                zr[i][0] = v.x; zr[i][1] = v.y; zr[i][2] = v.z; zr[i][3] = v.w;
            }
#pragma unroll
            for (int kk = 0; kk < 4; ++kk) {
                const int krow = kq * 4 + kk;
                float4 w0 = *(const float4*)&Ws[krow][tx * 4];
                float4 w1 = *(const float4*)&Ws[krow][128 + tx * 4];
                u64 w0a = packf2(w0.x, w0.y), w0b = packf2(w0.z, w0.w);
                u64 w1a = packf2(w1.x, w1.y), w1b = packf2(w1.z, w1.w);
#pragma unroll
                for (int i = 0; i < 8; ++i) {
                    u64 zz = packf2(zr[i][kk], zr[i][kk]);
                    fma2(acc0[i][0], zz, w0a);
                    fma2(acc0[i][1], zz, w0b);
                    fma2(acc1[i][0], zz, w1a);
                    fma2(acc1[i][1], zz, w1b);
                }
            }
        }
        __syncthreads();
    }

    // ---- store as fp16: 4 halves (8B) per thread per half-row ----
#pragma unroll
    for (int i = 0; i < 8; ++i) {
        int row = row0 + ty * 8 + i;
        if (row < N) {
            float a0, a1, a2, a3, b0, b1v, b2v, b3;
            unpackf2(acc0[i][0], a0, a1);
            unpackf2(acc0[i][1], a2, a3);
            unpackf2(acc1[i][0], b0, b1v);
            unpackf2(acc1[i][1], b2v, b3);
            __half2 pa0 = __floats2half2_rn(a0, a1);
            __half2 pa1 = __floats2half2_rn(a2, a3);
            __half2 pb0 = __floats2half2_rn(b0, b1v);
            __half2 pb1 = __floats2half2_rn(b2v, b3);
            uint2 sa, sb;
            sa.x = *(unsigned*)&pa0; sa.y = *(unsigned*)&pa1;
            sb.x = *(unsigned*)&pb0; sb.y = *(unsigned*)&pb1;
            *(uint2*)&g_AB[(size_t)row * 256 + tx * 4]       = sa;
            *(uint2*)&g_AB[(size_t)row * 256 + 128 + tx * 4] = sb;
        }
    }
}

// ---------------------------------------------------------------------------
// Edge kernel: 16 lanes per edge (2 edges/warp). Lane gl owns channels
// 8*gl .. 8*gl+7 -> one uint4 (16B = 8 halves) per half-row.
// ---------------------------------------------------------------------------
__global__ __launch_bounds__(256) void edge_score(
    const void* __restrict__ ei_raw,   // [2, E] int32 or int64 (see g_is64)
    const float* __restrict__ b1,      // [128]
    const float* __restrict__ W2,      // [128]
    const float* __restrict__ b2,      // [1]
    float* __restrict__ out,           // [E]
    int E, int N)
{
    const int lane = threadIdx.x & 31;
    const int gl   = lane & 15;                   // lane within edge-group
    const int warp = threadIdx.x >> 5;
    const int e = (blockIdx.x * 8 + warp) * 2 + (lane >> 4);
    if (e >= E) return;

    const float4 bbl = *(const float4*)(b1 + gl * 8);
    const float4 bbh = *(const float4*)(b1 + gl * 8 + 4);
    const float4 wwl = *(const float4*)(W2 + gl * 8);
    const float4 wwh = *(const float4*)(W2 + gl * 8 + 4);

    unsigned s, d;
    if (g_is64) {
        const long long* ei = (const long long*)ei_raw;
        s = (unsigned)ei[e];
        d = (unsigned)ei[(size_t)E + e];
    } else {
        const int* ei = (const int*)ei_raw;
        s = (unsigned)ei[e];
        d = (unsigned)ei[(size_t)E + e];
    }
    s = min(s, (unsigned)(N - 1));
    d = min(d, (unsigned)(N - 1));

    const uint4 ar = *(const uint4*)(g_AB + (size_t)s * 256 + gl * 8);
    const uint4 br = *(const uint4*)(g_AB + (size_t)d * 256 + 128 + gl * 8);
    const unsigned* au = (const unsigned*)&ar;
    const unsigned* bu = (const unsigned*)&br;

    const float bbf[8] = {bbl.x, bbl.y, bbl.z, bbl.w, bbh.x, bbh.y, bbh.z, bbh.w};
    const float wwf[8] = {wwl.x, wwl.y, wwl.z, wwl.w, wwh.x, wwh.y, wwh.z, wwh.w};

    float sum = 0.f;
#pragma unroll
    for (int i = 0; i < 4; ++i) {
        float2 a2 = __half22float2(*(const __half2*)&au[i]);
        float2 c2 = __half22float2(*(const __half2*)&bu[i]);
        float h0 = fmaxf(a2.x + c2.x + bbf[2 * i],     0.f);
        float h1 = fmaxf(a2.y + c2.y + bbf[2 * i + 1], 0.f);
        sum = fmaf(h0, wwf[2 * i],     sum);
        sum = fmaf(h1, wwf[2 * i + 1], sum);
    }

    // reduce across the 16-lane group (xor offsets < 16 stay in-group)
#pragma unroll
    for (int off = 8; off; off >>= 1)
        sum += __shfl_xor_sync(0xFFFFFFFFu, sum, off);

    if (gl == 0)
        out[e] = sum + __ldg(b2);
}

// ---------------------------------------------------------------------------
extern "C" void kernel_launch(void* const* d_in, const int* in_sizes, int n_in,
                              void* d_out, int out_size)
{
    const float* z   = (const float*)d_in[0];
    const void*  ei  = d_in[1];               // edge_index [2,E], dtype probed
    const float* W1  = (const float*)d_in[2];
    const float* b1  = (const float*)d_in[3];
    const float* W2  = (const float*)d_in[4];
    const float* b2  = (const float*)d_in[5];
    float*       out = (float*)d_out;

    const int N = in_sizes[0] / HID;   // 100000
    const int E = in_sizes[1] / 2;     // 1600000

    precompute_gemm<<<(N + 63) / 64, 256>>>(z, W1, (const int*)ei, N);

    // 16 edges per 256-thread block
    edge_score<<<(E + 15) / 16, 256>>>(ei, b1, W2, b2, out, E, N);
}

// round 4
// speedup vs baseline: 2.4991x; 1.8623x over previous
#include <cuda_runtime.h>
#include <cuda_fp16.h>
#include <cstdint>

// ---------------------------------------------------------------------------
// EdgeDecoder:
//   A'[n] = z[n] @ W1[0:128, :] + b1   (bias folded)
//   B[n]  = z[n] @ W1[128:256, :]
//   score[e] = relu(A'[src] + B[dst]) . W2 + b2
//
// Kernel 1: tensor-core GEMM [N,128]@[128,256] -> g_AB fp16.
//   Error-compensated fp16 split: z=zh+zl, W=Wh+Wl (fp16 each),
//   acc = Ah*Bh + Al*Bh + Ah*Bl in fp32  => fp32-grade input accuracy.
//   Block: 128 rows x 256 cols, 512 thr (16 warps, warp tile 64x32), K=128
//   fully in smem. Padded smem strides (136/264 halves) -> conflict-free
//   ldmatrix. Block 0 also probes edge_index dtype.
// Kernel 2: edge gather+relu+dot. 16 lanes/edge, 2 edges/warp, 8 iters/warp;
//   W2 held in registers across iters (kills the redundant L1tex wavefronts
//   that dominated R3's 89% l1tex).
// ---------------------------------------------------------------------------

#define HID 128
#define N_MAX 100000

__device__ __align__(16) __half g_AB[(size_t)N_MAX * 256];
__device__ int g_is64;

// ---- tensor-core primitives ----
__device__ __forceinline__ void ldsm4(unsigned* r, const void* p) {
    unsigned a = (unsigned)__cvta_generic_to_shared(p);
    asm volatile("ldmatrix.sync.aligned.m8n8.x4.shared.b16 {%0,%1,%2,%3},[%4];"
                 : "=r"(r[0]), "=r"(r[1]), "=r"(r[2]), "=r"(r[3]) : "r"(a));
}
__device__ __forceinline__ void ldsm2t(unsigned* r, const void* p) {
    unsigned a = (unsigned)__cvta_generic_to_shared(p);
    asm volatile("ldmatrix.sync.aligned.m8n8.x2.trans.shared.b16 {%0,%1},[%2];"
                 : "=r"(r[0]), "=r"(r[1]) : "r"(a));
}
__device__ __forceinline__ void mma16816(float* c, const unsigned* a, const unsigned* b) {
    asm volatile(
        "mma.sync.aligned.m16n8k16.row.col.f32.f16.f16.f32 "
        "{%0,%1,%2,%3},{%4,%5,%6,%7},{%8,%9},{%0,%1,%2,%3};"
        : "+f"(c[0]), "+f"(c[1]), "+f"(c[2]), "+f"(c[3])
        : "r"(a[0]), "r"(a[1]), "r"(a[2]), "r"(a[3]), "r"(b[0]), "r"(b[1]));
}

// smem strides in halves (row byte strides 272 / 528: 16B shift/row -> no bank conflicts)
#define ZS 136
#define WS 264
#define SMEM_BYTES ((2 * 128 * WS + 2 * 128 * ZS) * 2)

// ---------------------------------------------------------------------------
__global__ __launch_bounds__(512, 1) void gemm_tc(
    const float* __restrict__ z,    // [N,128]
    const float* __restrict__ W1,   // [256,128]
    const float* __restrict__ b1,   // [128]
    const int*   __restrict__ ei32, // edge_index as int32 (dtype probe)
    int N)
{
    // dtype probe (consumed only by the NEXT kernel)
    if (blockIdx.x == 0 && threadIdx.x == 0) {
        int all0 = 1;
#pragma unroll
        for (int i = 0; i < 8; ++i) all0 &= (ei32[2 * i + 1] == 0);
        g_is64 = all0;
    }

    extern __shared__ __align__(16) char dynsmem[];
    __half* Whi = (__half*)dynsmem;        // [128][WS]
    __half* Wlo = Whi + 128 * WS;
    __half* Zhi = Wlo + 128 * WS;          // [128][ZS]
    __half* Zlo = Zhi + 128 * ZS;

    const int t    = threadIdx.x;
    const int lane = t & 31;
    const int w    = t >> 5;
    const int row0 = blockIdx.x * 128;

    // ---- fill W hi/lo: Wbig[k][j] = (j<128) ? W1[k][j] : W1[128+k][j-128] ----
#pragma unroll
    for (int i = 0; i < 64; ++i) {
        int idx = t + i * 512;             // 0..32767
        int k = idx >> 8, j = idx & 255;
        float f = (j < 128) ? W1[(size_t)k * 128 + j]
                            : W1[(size_t)(128 + k) * 128 + (j - 128)];
        __half h = __float2half_rn(f);
        Whi[k * WS + j] = h;
        Wlo[k * WS + j] = __float2half_rn(f - __half2float(h));
    }
    // ---- fill Z hi/lo (128 rows x 128) ----
#pragma unroll
    for (int i = 0; i < 8; ++i) {
        int idx4 = t + i * 512;            // 0..4095 float4s
        int r = idx4 >> 5, c = (idx4 & 31) * 4;
        int gr = row0 + r; if (gr >= N) gr = N - 1;
        float4 v = *(const float4*)(z + (size_t)gr * HID + c);
        float f[4] = {v.x, v.y, v.z, v.w};
#pragma unroll
        for (int q = 0; q < 4; ++q) {
            __half h = __float2half_rn(f[q]);
            Zhi[r * ZS + c + q] = h;
            Zlo[r * ZS + c + q] = __float2half_rn(f[q] - __half2float(h));
        }
    }
    __syncthreads();

    // ---- warp tiling: 16 warps = 2 (m) x 8 (n); warp tile 64 rows x 32 cols ----
    const int wm = w >> 3;                 // 0..1
    const int wn = w & 7;                  // 0..7
    const int mbase = wm * 64;
    const int nbase = wn * 32;

    float acc[4][4][4];
#pragma unroll
    for (int mt = 0; mt < 4; ++mt)
#pragma unroll
        for (int nt = 0; nt < 4; ++nt)
#pragma unroll
            for (int q = 0; q < 4; ++q) acc[mt][nt][q] = 0.f;

    const int arow = lane & 15;
    const int acol8 = (lane >> 4) << 3;
    const int brow = lane & 15;            // lanes 0..15 feed x2 addresses

#pragma unroll
    for (int ks = 0; ks < 8; ++ks) {
        const int k0 = ks * 16;
        unsigned ah[4][4], al[4][4];
#pragma unroll
        for (int mt = 0; mt < 4; ++mt) {
            const int rr = (mbase + mt * 16 + arow) * ZS + k0 + acol8;
            ldsm4(ah[mt], Zhi + rr);
            ldsm4(al[mt], Zlo + rr);
        }
#pragma unroll
        for (int nt = 0; nt < 4; ++nt) {
            unsigned bb[2];
            const int wr = (k0 + brow) * WS + nbase + nt * 8;
            ldsm2t(bb, Whi + wr);
#pragma unroll
            for (int mt = 0; mt < 4; ++mt) {
                mma16816(acc[mt][nt], ah[mt], bb);
                mma16816(acc[mt][nt], al[mt], bb);
            }
            ldsm2t(bb, Wlo + wr);
#pragma unroll
            for (int mt = 0; mt < 4; ++mt)
                mma16816(acc[mt][nt], ah[mt], bb);
        }
    }

    // ---- epilogue: +b1 on A half (cols<128), fp16 store ----
    const int g  = lane >> 2;
    const int c2 = (lane & 3) * 2;
#pragma unroll
    for (int nt = 0; nt < 4; ++nt) {
        const int col = nbase + nt * 8 + c2;
        float bx = 0.f, by = 0.f;
        if (col < 128) { bx = __ldg(b1 + col); by = __ldg(b1 + col + 1); }
#pragma unroll
        for (int mt = 0; mt < 4; ++mt) {
            const int row = row0 + mbase + mt * 16 + g;
            if (row < N) {
                __half2 h0 = __floats2half2_rn(acc[mt][nt][0] + bx, acc[mt][nt][1] + by);
                *(__half2*)&g_AB[(size_t)row * 256 + col] = h0;
            }
            if (row + 8 < N) {
                __half2 h1 = __floats2half2_rn(acc[mt][nt][2] + bx, acc[mt][nt][3] + by);
                *(__half2*)&g_AB[(size_t)(row + 8) * 256 + col] = h1;
            }
        }
    }
}

// ---------------------------------------------------------------------------
// Edge kernel: 16 lanes/edge, 2 edges/warp, ITER edges-pairs per warp.
// W2/b2 in registers across iterations.
// ---------------------------------------------------------------------------
#define EDGE_ITER 8

__global__ __launch_bounds__(256) void edge_score(
    const void* __restrict__ ei_raw,   // [2,E] int32 or int64 (g_is64)
    const float* __restrict__ W2,      // [128]
    const float* __restrict__ b2,      // [1]
    float* __restrict__ out,           // [E]
    int E, int N)
{
    const int lane = threadIdx.x & 31;
    const int gl   = lane & 15;
    const int warp = threadIdx.x >> 5;
    const int ebase = (blockIdx.x * 8 + warp) * (2 * EDGE_ITER) + (lane >> 4);

    const float4 wwl = *(const float4*)(W2 + gl * 8);
    const float4 wwh = *(const float4*)(W2 + gl * 8 + 4);
    const float wwf[8] = {wwl.x, wwl.y, wwl.z, wwl.w, wwh.x, wwh.y, wwh.z, wwh.w};
    const float bias2 = __ldg(b2);
    const int is64 = g_is64;

#pragma unroll
    for (int it = 0; it < EDGE_ITER; ++it) {
        const int e = ebase + it * 2;
        if (e >= E) return;

        unsigned s, d;
        if (is64) {
            const long long* ei = (const long long*)ei_raw;
            s = (unsigned)ei[e];
            d = (unsigned)ei[(size_t)E + e];
        } else {
            const int* ei = (const int*)ei_raw;
            s = (unsigned)ei[e];
            d = (unsigned)ei[(size_t)E + e];
        }
        s = min(s, (unsigned)(N - 1));
        d = min(d, (unsigned)(N - 1));

        const uint4 ar = *(const uint4*)(g_AB + (size_t)s * 256 + gl * 8);
        const uint4 br = *(const uint4*)(g_AB + (size_t)d * 256 + 128 + gl * 8);
        const unsigned* au = (const unsigned*)&ar;
        const unsigned* bu = (const unsigned*)&br;

        float sum = 0.f;
#pragma unroll
        for (int i = 0; i < 4; ++i) {
            float2 a2 = __half22float2(*(const __half2*)&au[i]);
            float2 c2 = __half22float2(*(const __half2*)&bu[i]);
            float h0 = fmaxf(a2.x + c2.x, 0.f);
            float h1 = fmaxf(a2.y + c2.y, 0.f);
            sum = fmaf(h0, wwf[2 * i],     sum);
            sum = fmaf(h1, wwf[2 * i + 1], sum);
        }
#pragma unroll
        for (int off = 8; off; off >>= 1)
            sum += __shfl_xor_sync(0xFFFFFFFFu, sum, off);

        if (gl == 0)
            out[e] = sum + bias2;
    }
}

// ---------------------------------------------------------------------------
extern "C" void kernel_launch(void* const* d_in, const int* in_sizes, int n_in,
                              void* d_out, int out_size)
{
    const float* z   = (const float*)d_in[0];
    const void*  ei  = d_in[1];
    const float* W1  = (const float*)d_in[2];
    const float* b1  = (const float*)d_in[3];
    const float* W2  = (const float*)d_in[4];
    const float* b2  = (const float*)d_in[5];
    float*       out = (float*)d_out;

    const int N = in_sizes[0] / HID;   // 100000
    const int E = in_sizes[1] / 2;     // 1600000

    static int smem_set = 0;
    if (!smem_set) {
        cudaFuncSetAttribute(gemm_tc, cudaFuncAttributeMaxDynamicSharedMemorySize,
                             SMEM_BYTES);
        smem_set = 1;
    }

    gemm_tc<<<(N + 127) / 128, 512, SMEM_BYTES>>>(z, W1, b1, (const int*)ei, N);

    // 8 warps/block, 2 edges/warp/iter, EDGE_ITER iters -> 128 edges/block
    const int edges_per_block = 8 * 2 * EDGE_ITER;
    edge_score<<<(E + edges_per_block - 1) / edges_per_block, 256>>>(
        ei, W2, b2, out, E, N);
}

// round 5
// speedup vs baseline: 3.0854x; 1.2346x over previous
#include <cuda_runtime.h>
#include <cuda_fp16.h>
#include <cstdint>

// ---------------------------------------------------------------------------
// EdgeDecoder:
//   A'[n] = z[n] @ W1[0:128,:] + b1 ; B[n] = z[n] @ W1[128:256,:]
//   score[e] = relu(A'[src] + B[dst]) . W2 + b2
//
// Kernel 0 (prep): W1 -> fp16 hi/lo split in fused [128][256] layout, once.
//                  Also probes edge_index dtype.
// Kernel 1 (gemm): persistent (grid=148). W hi/lo smem-resident across all
//   row-strips; per strip: z fill (fp16 split), 3-term compensated HMMA
//   (Ah*Bh + Al*Bh + Ah*Bl, fp32 acc), stmatrix epilogue -> coalesced STG.128.
// Kernel 2 (edge): 16 lanes/edge, 2 edges/warp, 8 iters; W2 in regs;
//   half2 add/relu (HADD2/HMNMX2), fp32 dot.
// ---------------------------------------------------------------------------

#define HID 128
#define N_MAX 100000

__device__ __align__(16) __half g_AB[(size_t)N_MAX * 256];
__device__ __align__(16) __half g_Whi[128 * 256];
__device__ __align__(16) __half g_Wlo[128 * 256];
__device__ int g_is64;

// ---- tensor-core primitives ----
__device__ __forceinline__ void ldsm4(unsigned* r, const void* p) {
    unsigned a = (unsigned)__cvta_generic_to_shared(p);
    asm volatile("ldmatrix.sync.aligned.m8n8.x4.shared.b16 {%0,%1,%2,%3},[%4];"
                 : "=r"(r[0]), "=r"(r[1]), "=r"(r[2]), "=r"(r[3]) : "r"(a));
}
__device__ __forceinline__ void ldsm2t(unsigned* r, const void* p) {
    unsigned a = (unsigned)__cvta_generic_to_shared(p);
    asm volatile("ldmatrix.sync.aligned.m8n8.x2.trans.shared.b16 {%0,%1},[%2];"
                 : "=r"(r[0]), "=r"(r[1]) : "r"(a));
}
__device__ __forceinline__ void stsm4(void* p, unsigned r0, unsigned r1,
                                      unsigned r2, unsigned r3) {
    unsigned a = (unsigned)__cvta_generic_to_shared(p);
    asm volatile("stmatrix.sync.aligned.m8n8.x4.shared.b16 [%0],{%1,%2,%3,%4};"
                 :: "r"(a), "r"(r0), "r"(r1), "r"(r2), "r"(r3));
}
__device__ __forceinline__ void mma16816(float* c, const unsigned* a, const unsigned* b) {
    asm volatile(
        "mma.sync.aligned.m16n8k16.row.col.f32.f16.f16.f32 "
        "{%0,%1,%2,%3},{%4,%5,%6,%7},{%8,%9},{%0,%1,%2,%3};"
        : "+f"(c[0]), "+f"(c[1]), "+f"(c[2]), "+f"(c[3])
        : "r"(a[0]), "r"(a[1]), "r"(a[2]), "r"(a[3]), "r"(b[0]), "r"(b[1]));
}

// smem strides in halves; row byte strides 272/528 -> 16B shift/row, conflict-free
#define ZS 136
#define WS 264
#define SMEM_BYTES ((2 * 128 * WS + 2 * 128 * ZS) * 2)

// ---------------------------------------------------------------------------
// Prep: fused-layout fp16 hi/lo W + dtype probe.
// ---------------------------------------------------------------------------
__global__ __launch_bounds__(512) void prep_w(
    const float* __restrict__ W1, const int* __restrict__ ei32)
{
    if (blockIdx.x == 0 && threadIdx.x == 0) {
        int all0 = 1;
#pragma unroll
        for (int i = 0; i < 8; ++i) all0 &= (ei32[2 * i + 1] == 0);
        g_is64 = all0;
    }
    int idx = blockIdx.x * 512 + threadIdx.x;   // grid 64 -> 32768
    int k = idx >> 8, j = idx & 255;
    float f = (j < 128) ? W1[(size_t)k * 128 + j]
                        : W1[(size_t)(128 + k) * 128 + (j - 128)];
    __half h = __float2half_rn(f);
    g_Whi[idx] = h;
    g_Wlo[idx] = __float2half_rn(f - __half2float(h));
}

// ---------------------------------------------------------------------------
// Persistent GEMM.
// ---------------------------------------------------------------------------
__global__ __launch_bounds__(512, 1) void gemm_tc(
    const float* __restrict__ z,    // [N,128]
    const float* __restrict__ b1,   // [128]
    int N, int nstrips)
{
    extern __shared__ __align__(16) char dynsmem[];
    __half* Whi = (__half*)dynsmem;            // [128][WS]
    __half* Wlo = Whi + 128 * WS;
    __half* Zhi = Wlo + 128 * WS;              // [128][ZS]
    __half* Zlo = Zhi + 128 * ZS;
    __half* Stage = Zhi;                       // overlay: [128][WS] (fits in Z area? no ->
    // Stage uses its own stride OS=264 but spans 128*264*2=67.6KB <= Z area 69.6KB)
#define OS 264

    const int t    = threadIdx.x;
    const int lane = t & 31;
    const int w    = t >> 5;

    // ---- load W hi/lo into smem once (uint4 copies) ----
#pragma unroll
    for (int i = 0; i < 8; ++i) {
        int idx = t + i * 512;                 // 0..4095 uint4s
        int row = idx >> 5, c16 = idx & 31;    // 32 uint4 per 256-half row
        *(uint4*)&Whi[row * WS + c16 * 8] = *(const uint4*)&g_Whi[row * 256 + c16 * 8];
        *(uint4*)&Wlo[row * WS + c16 * 8] = *(const uint4*)&g_Wlo[row * 256 + c16 * 8];
    }
    __syncthreads();

    const int wm = w >> 3, wn = w & 7;
    const int mbase = wm * 64, nbase = wn * 32;
    const int arow = lane & 15, acol8 = (lane >> 4) << 3;
    const int brow = lane & 15;

    // bias regs for this warp's columns (A half only: wn<4)
    float bx[4], by[4];
#pragma unroll
    for (int nt = 0; nt < 4; ++nt) {
        int col = nbase + nt * 8 + (lane & 3) * 2;
        bx[nt] = (wn < 4) ? __ldg(b1 + col)     : 0.f;
        by[nt] = (wn < 4) ? __ldg(b1 + col + 1) : 0.f;
    }

    for (int strip = blockIdx.x; strip < nstrips; strip += gridDim.x) {
        const int row0 = strip * 128;

        // ---- Z fill: fp32 -> fp16 hi/lo ----
#pragma unroll
        for (int i = 0; i < 8; ++i) {
            int idx4 = t + i * 512;            // 0..4095 float4s
            int r = idx4 >> 5, c = (idx4 & 31) * 4;
            int gr = row0 + r; if (gr >= N) gr = N - 1;
            float4 v = *(const float4*)(z + (size_t)gr * HID + c);
            __half2 h0 = __floats2half2_rn(v.x, v.y);
            __half2 h1 = __floats2half2_rn(v.z, v.w);
            float2 f0 = __half22float2(h0), f1 = __half22float2(h1);
            __half2 l0 = __floats2half2_rn(v.x - f0.x, v.y - f0.y);
            __half2 l1 = __floats2half2_rn(v.z - f1.x, v.w - f1.y);
            uint2 sh, sl;
            sh.x = *(unsigned*)&h0; sh.y = *(unsigned*)&h1;
            sl.x = *(unsigned*)&l0; sl.y = *(unsigned*)&l1;
            *(uint2*)&Zhi[r * ZS + c] = sh;
            *(uint2*)&Zlo[r * ZS + c] = sl;
        }
        __syncthreads();

        // ---- compute: 3-term compensated ----
        float acc[4][4][4];
#pragma unroll
        for (int mt = 0; mt < 4; ++mt)
#pragma unroll
            for (int nt = 0; nt < 4; ++nt)
#pragma unroll
                for (int q = 0; q < 4; ++q) acc[mt][nt][q] = 0.f;

#pragma unroll
        for (int ks = 0; ks < 8; ++ks) {
            const int k0 = ks * 16;
            unsigned ah[4][4], al[4][4];
#pragma unroll
            for (int mt = 0; mt < 4; ++mt) {
                const int rr = (mbase + mt * 16 + arow) * ZS + k0 + acol8;
                ldsm4(ah[mt], Zhi + rr);
                ldsm4(al[mt], Zlo + rr);
            }
#pragma unroll
            for (int nt = 0; nt < 4; ++nt) {
                unsigned bb[2];
                const int wr = (k0 + brow) * WS + nbase + nt * 8;
                ldsm2t(bb, Whi + wr);
#pragma unroll
                for (int mt = 0; mt < 4; ++mt) {
                    mma16816(acc[mt][nt], ah[mt], bb);
                    mma16816(acc[mt][nt], al[mt], bb);
                }
                ldsm2t(bb, Wlo + wr);
#pragma unroll
                for (int mt = 0; mt < 4; ++mt)
                    mma16816(acc[mt][nt], ah[mt], bb);
            }
        }
        __syncthreads();   // all warps done reading Z before Stage overwrite

        // ---- stmatrix epilogue into Stage ----
        const int stile = lane >> 3;           // tile index 0..3 (nt)
        const int srow  = lane & 7;
#pragma unroll
        for (int mt = 0; mt < 4; ++mt) {
            __half2 u[4], l[4];
#pragma unroll
            for (int nt = 0; nt < 4; ++nt) {
                u[nt] = __floats2half2_rn(acc[mt][nt][0] + bx[nt], acc[mt][nt][1] + by[nt]);
                l[nt] = __floats2half2_rn(acc[mt][nt][2] + bx[nt], acc[mt][nt][3] + by[nt]);
            }
            __half* pu = Stage + (mbase + mt * 16 + srow) * OS + nbase + stile * 8;
            __half* pl = Stage + (mbase + mt * 16 + 8 + srow) * OS + nbase + stile * 8;
            stsm4(pu, *(unsigned*)&u[0], *(unsigned*)&u[1], *(unsigned*)&u[2], *(unsigned*)&u[3]);
            stsm4(pl, *(unsigned*)&l[0], *(unsigned*)&l[1], *(unsigned*)&l[2], *(unsigned*)&l[3]);
        }
        __syncthreads();

        // ---- coalesced copy Stage -> g_AB ----
#pragma unroll
        for (int i = 0; i < 8; ++i) {
            int idx = t + i * 512;             // 0..4095 uint4s
            int r = idx >> 5, c16 = idx & 31;
            int gr = row0 + r;
            if (gr < N) {
                uint4 v = *(const uint4*)&Stage[r * OS + c16 * 8];
                *(uint4*)&g_AB[(size_t)gr * 256 + c16 * 8] = v;
            }
        }
        __syncthreads();   // copy done before next strip's Z fill reuses area
    }
}

// ---------------------------------------------------------------------------
// Edge kernel: 16 lanes/edge, 2 edges/warp, 8 iters; half2 add/relu, fp32 dot.
// ---------------------------------------------------------------------------
#define EDGE_ITER 8

__global__ __launch_bounds__(256) void edge_score(
    const void* __restrict__ ei_raw,
    const float* __restrict__ W2,
    const float* __restrict__ b2,
    float* __restrict__ out,
    int E, int N)
{
    const int lane = threadIdx.x & 31;
    const int gl   = lane & 15;
    const int warp = threadIdx.x >> 5;
    const int ebase = (blockIdx.x * 8 + warp) * (2 * EDGE_ITER) + (lane >> 4);

    const float4 wwl = *(const float4*)(W2 + gl * 8);
    const float4 wwh = *(const float4*)(W2 + gl * 8 + 4);
    const float wwf[8] = {wwl.x, wwl.y, wwl.z, wwl.w, wwh.x, wwh.y, wwh.z, wwh.w};
    const float bias2 = __ldg(b2);
    const int is64 = g_is64;
    const __half2 zero2 = __float2half2_rn(0.f);

#pragma unroll
    for (int it = 0; it < EDGE_ITER; ++it) {
        const int e = ebase + it * 2;
        if (e >= E) return;

        unsigned s, d;
        if (is64) {
            const long long* ei = (const long long*)ei_raw;
            s = (unsigned)ei[e];
            d = (unsigned)ei[(size_t)E + e];
        } else {
            const int* ei = (const int*)ei_raw;
            s = (unsigned)ei[e];
            d = (unsigned)ei[(size_t)E + e];
        }
        s = min(s, (unsigned)(N - 1));
        d = min(d, (unsigned)(N - 1));

        const uint4 ar = *(const uint4*)(g_AB + (size_t)s * 256 + gl * 8);
        const uint4 br = *(const uint4*)(g_AB + (size_t)d * 256 + 128 + gl * 8);
        const unsigned* au = (const unsigned*)&ar;
        const unsigned* bu = (const unsigned*)&br;

        float sum = 0.f;
#pragma unroll
        for (int i = 0; i < 4; ++i) {
            __half2 r = __hmax2(__hadd2(*(const __half2*)&au[i],
                                        *(const __half2*)&bu[i]), zero2);
            float2 f = __half22float2(r);
            sum = fmaf(f.x, wwf[2 * i],     sum);
            sum = fmaf(f.y, wwf[2 * i + 1], sum);
        }
#pragma unroll
        for (int off = 8; off; off >>= 1)
            sum += __shfl_xor_sync(0xFFFFFFFFu, sum, off);

        if (gl == 0)
            out[e] = sum + bias2;
    }
}

// ---------------------------------------------------------------------------
extern "C" void kernel_launch(void* const* d_in, const int* in_sizes, int n_in,
                              void* d_out, int out_size)
{
    const float* z   = (const float*)d_in[0];
    const void*  ei  = d_in[1];
    const float* W1  = (const float*)d_in[2];
    const float* b1  = (const float*)d_in[3];
    const float* W2  = (const float*)d_in[4];
    const float* b2  = (const float*)d_in[5];
    float*       out = (float*)d_out;

    const int N = in_sizes[0] / HID;   // 100000
    const int E = in_sizes[1] / 2;     // 1600000

    static int smem_set = 0;
    if (!smem_set) {
        cudaFuncSetAttribute(gemm_tc, cudaFuncAttributeMaxDynamicSharedMemorySize,
                             SMEM_BYTES);
        smem_set = 1;
    }

    prep_w<<<64, 512>>>(W1, (const int*)ei);

    const int nstrips = (N + 127) / 128;
    gemm_tc<<<148, 512, SMEM_BYTES>>>(z, b1, N, nstrips);

    const int edges_per_block = 8 * 2 * EDGE_ITER;   // 128
    edge_score<<<(E + edges_per_block - 1) / edges_per_block, 256>>>(
        ei, W2, b2, out, E, N);
}

// round 6
// speedup vs baseline: 3.6266x; 1.1754x over previous
#include <cuda_runtime.h>
#include <cuda_fp16.h>
#include <cstdint>

// ---------------------------------------------------------------------------
// EdgeDecoder:
//   A'[n] = z[n] @ W1[0:128,:] + b1 ; B[n] = z[n] @ W1[128:256,:]
//   score[e] = relu(A'[src] + B[dst]) . W2 + b2
//
// Kernel 0 (prep): W1 -> fp16 (single) fused [128][256] layout, once.
//                  Also probes edge_index dtype.
// Kernel 1 (gemm): persistent (grid=148). W fp16 smem-resident; per strip:
//   z fp16 hi/lo split fill, 2-term compensated HMMA (Ah*Bh + Al*Bh, fp32
//   acc -> z at fp32-grade, W at fp16 grade ~ matches AB-storage error),
//   stmatrix epilogue -> coalesced STG.128.
// Kernel 2 (edge): 16 lanes/edge, 2 edges/warp, 8 iters; W2 in regs;
//   half2 add/relu, fp32 dot.
// ---------------------------------------------------------------------------

#define HID 128
#define N_MAX 100000

__device__ __align__(16) __half g_AB[(size_t)N_MAX * 256];
__device__ __align__(16) __half g_Whi[128 * 256];
__device__ int g_is64;

// ---- tensor-core primitives ----
__device__ __forceinline__ void ldsm4(unsigned* r, const void* p) {
    unsigned a = (unsigned)__cvta_generic_to_shared(p);
    asm volatile("ldmatrix.sync.aligned.m8n8.x4.shared.b16 {%0,%1,%2,%3},[%4];"
                 : "=r"(r[0]), "=r"(r[1]), "=r"(r[2]), "=r"(r[3]) : "r"(a));
}
__device__ __forceinline__ void ldsm2t(unsigned* r, const void* p) {
    unsigned a = (unsigned)__cvta_generic_to_shared(p);
    asm volatile("ldmatrix.sync.aligned.m8n8.x2.trans.shared.b16 {%0,%1},[%2];"
                 : "=r"(r[0]), "=r"(r[1]) : "r"(a));
}
__device__ __forceinline__ void stsm4(void* p, unsigned r0, unsigned r1,
                                      unsigned r2, unsigned r3) {
    unsigned a = (unsigned)__cvta_generic_to_shared(p);
    asm volatile("stmatrix.sync.aligned.m8n8.x4.shared.b16 [%0],{%1,%2,%3,%4};"
                 :: "r"(a), "r"(r0), "r"(r1), "r"(r2), "r"(r3));
}
__device__ __forceinline__ void mma16816(float* c, const unsigned* a, const unsigned* b) {
    asm volatile(
        "mma.sync.aligned.m16n8k16.row.col.f32.f16.f16.f32 "
        "{%0,%1,%2,%3},{%4,%5,%6,%7},{%8,%9},{%0,%1,%2,%3};"
        : "+f"(c[0]), "+f"(c[1]), "+f"(c[2]), "+f"(c[3])
        : "r"(a[0]), "r"(a[1]), "r"(a[2]), "r"(a[3]), "r"(b[0]), "r"(b[1]));
}

// smem strides in halves; row byte strides 272/528 -> 16B shift/row, conflict-free
#define ZS 136
#define WS 264
#define OS 264
#define SMEM_BYTES ((128 * WS + 2 * 128 * ZS) * 2)   // 137,216 B

// ---------------------------------------------------------------------------
// Prep: fused-layout fp16 W + dtype probe.
// ---------------------------------------------------------------------------
__global__ __launch_bounds__(512) void prep_w(
    const float* __restrict__ W1, const int* __restrict__ ei32)
{
    if (blockIdx.x == 0 && threadIdx.x == 0) {
        int all0 = 1;
#pragma unroll
        for (int i = 0; i < 8; ++i) all0 &= (ei32[2 * i + 1] == 0);
        g_is64 = all0;
    }
    int idx = blockIdx.x * 512 + threadIdx.x;   // grid 64 -> 32768
    int k = idx >> 8, j = idx & 255;
    float f = (j < 128) ? W1[(size_t)k * 128 + j]
                        : W1[(size_t)(128 + k) * 128 + (j - 128)];
    g_Whi[idx] = __float2half_rn(f);
}

// ---------------------------------------------------------------------------
// Persistent GEMM, 2-term compensated.
// ---------------------------------------------------------------------------
__global__ __launch_bounds__(512, 1) void gemm_tc(
    const float* __restrict__ z,    // [N,128]
    const float* __restrict__ b1,   // [128]
    int N, int nstrips)
{
    extern __shared__ __align__(16) char dynsmem[];
    __half* Whi = (__half*)dynsmem;            // [128][WS]
    __half* Zhi = Whi + 128 * WS;              // [128][ZS]
    __half* Zlo = Zhi + 128 * ZS;
    __half* Stage = Zhi;                       // overlay [128][OS] over Zhi+Zlo
                                               // (67.6KB <= 69.6KB)

    const int t    = threadIdx.x;
    const int lane = t & 31;
    const int w    = t >> 5;

    // ---- load W fp16 into smem once (uint4 copies) ----
#pragma unroll
    for (int i = 0; i < 4; ++i) {
        int idx = t + i * 512;                 // 0..2047 uint4s
        int row = idx >> 4, c16 = idx & 15;    // 16 uint4 per 128... no:
        // 256 halves/row = 32 uint4/row; 2048 uint4 = 64 rows?? -> redo:
        // total 128*256 halves = 4096 uint4; with hi only it's 4096/?? ->
        // 128 rows * 32 uint4 = 4096 uint4. Need i<8.
        (void)row; (void)c16;
    }
    // (correct W fill: 4096 uint4 over 512 threads -> 8 iters)
#pragma unroll
    for (int i = 0; i < 8; ++i) {
        int idx = t + i * 512;                 // 0..4095
        int row = idx >> 5, c16 = idx & 31;
        *(uint4*)&Whi[row * WS + c16 * 8] = *(const uint4*)&g_Whi[row * 256 + c16 * 8];
    }
    __syncthreads();

    const int wm = w >> 3, wn = w & 7;
    const int mbase = wm * 64, nbase = wn * 32;
    const int arow = lane & 15, acol8 = (lane >> 4) << 3;
    const int brow = lane & 15;

    // bias regs for this warp's columns (A half only: wn<4)
    float bx[4], by[4];
#pragma unroll
    for (int nt = 0; nt < 4; ++nt) {
        int col = nbase + nt * 8 + (lane & 3) * 2;
        bx[nt] = (wn < 4) ? __ldg(b1 + col)     : 0.f;
        by[nt] = (wn < 4) ? __ldg(b1 + col + 1) : 0.f;
    }

    for (int strip = blockIdx.x; strip < nstrips; strip += gridDim.x) {
        const int row0 = strip * 128;

        // ---- Z fill: fp32 -> fp16 hi/lo ----
#pragma unroll
        for (int i = 0; i < 8; ++i) {
            int idx4 = t + i * 512;            // 0..4095 float4s
            int r = idx4 >> 5, c = (idx4 & 31) * 4;
            int gr = row0 + r; if (gr >= N) gr = N - 1;
            float4 v = *(const float4*)(z + (size_t)gr * HID + c);
            __half2 h0 = __floats2half2_rn(v.x, v.y);
            __half2 h1 = __floats2half2_rn(v.z, v.w);
            float2 f0 = __half22float2(h0), f1 = __half22float2(h1);
            __half2 l0 = __floats2half2_rn(v.x - f0.x, v.y - f0.y);
            __half2 l1 = __floats2half2_rn(v.z - f1.x, v.w - f1.y);
            uint2 sh, sl;
            sh.x = *(unsigned*)&h0; sh.y = *(unsigned*)&h1;
            sl.x = *(unsigned*)&l0; sl.y = *(unsigned*)&l1;
            *(uint2*)&Zhi[r * ZS + c] = sh;
            *(uint2*)&Zlo[r * ZS + c] = sl;
        }
        __syncthreads();

        // ---- compute: 2-term compensated (Ah*Bh + Al*Bh) ----
        float acc[4][4][4];
#pragma unroll
        for (int mt = 0; mt < 4; ++mt)
#pragma unroll
            for (int nt = 0; nt < 4; ++nt)
#pragma unroll
                for (int q = 0; q < 4; ++q) acc[mt][nt][q] = 0.f;

#pragma unroll
        for (int ks = 0; ks < 8; ++ks) {
            const int k0 = ks * 16;
            unsigned ah[4][4], al[4][4];
#pragma unroll
            for (int mt = 0; mt < 4; ++mt) {
                const int rr = (mbase + mt * 16 + arow) * ZS + k0 + acol8;
                ldsm4(ah[mt], Zhi + rr);
                ldsm4(al[mt], Zlo + rr);
            }
#pragma unroll
            for (int nt = 0; nt < 4; ++nt) {
                unsigned bb[2];
                const int wr = (k0 + brow) * WS + nbase + nt * 8;
                ldsm2t(bb, Whi + wr);
#pragma unroll
                for (int mt = 0; mt < 4; ++mt) {
                    mma16816(acc[mt][nt], ah[mt], bb);
                    mma16816(acc[mt][nt], al[mt], bb);
                }
            }
        }
        __syncthreads();   // all warps done reading Z before Stage overwrite

        // ---- stmatrix epilogue into Stage ----
        const int stile = lane >> 3;
        const int srow  = lane & 7;
#pragma unroll
        for (int mt = 0; mt < 4; ++mt) {
            __half2 u[4], l[4];
#pragma unroll
            for (int nt = 0; nt < 4; ++nt) {
                u[nt] = __floats2half2_rn(acc[mt][nt][0] + bx[nt], acc[mt][nt][1] + by[nt]);
                l[nt] = __floats2half2_rn(acc[mt][nt][2] + bx[nt], acc[mt][nt][3] + by[nt]);
            }
            __half* pu = Stage + (mbase + mt * 16 + srow) * OS + nbase + stile * 8;
            __half* pl = Stage + (mbase + mt * 16 + 8 + srow) * OS + nbase + stile * 8;
            stsm4(pu, *(unsigned*)&u[0], *(unsigned*)&u[1], *(unsigned*)&u[2], *(unsigned*)&u[3]);
            stsm4(pl, *(unsigned*)&l[0], *(unsigned*)&l[1], *(unsigned*)&l[2], *(unsigned*)&l[3]);
        }
        __syncthreads();

        // ---- coalesced copy Stage -> g_AB ----
#pragma unroll
        for (int i = 0; i < 8; ++i) {
            int idx = t + i * 512;             // 0..4095 uint4s
            int r = idx >> 5, c16 = idx & 31;
            int gr = row0 + r;
            if (gr < N) {
                uint4 v = *(const uint4*)&Stage[r * OS + c16 * 8];
                *(uint4*)&g_AB[(size_t)gr * 256 + c16 * 8] = v;
            }
        }
        __syncthreads();   // copy done before next strip's Z fill reuses area
    }
}

// ---------------------------------------------------------------------------
// Edge kernel: 16 lanes/edge, 2 edges/warp, 8 iters; half2 add/relu, fp32 dot.
// ---------------------------------------------------------------------------
#define EDGE_ITER 8

__global__ __launch_bounds__(256) void edge_score(
    const void* __restrict__ ei_raw,
    const float* __restrict__ W2,
    const float* __restrict__ b2,
    float* __restrict__ out,
    int E, int N)
{
    const int lane = threadIdx.x & 31;
    const int gl   = lane & 15;
    const int warp = threadIdx.x >> 5;
    const int ebase = (blockIdx.x * 8 + warp) * (2 * EDGE_ITER) + (lane >> 4);

    const float4 wwl = *(const float4*)(W2 + gl * 8);
    const float4 wwh = *(const float4*)(W2 + gl * 8 + 4);
    const float wwf[8] = {wwl.x, wwl.y, wwl.z, wwl.w, wwh.x, wwh.y, wwh.z, wwh.w};
    const float bias2 = __ldg(b2);
    const int is64 = g_is64;
    const __half2 zero2 = __float2half2_rn(0.f);

#pragma unroll
    for (int it = 0; it < EDGE_ITER; ++it) {
        const int e = ebase + it * 2;
        if (e >= E) return;

        unsigned s, d;
        if (is64) {
            const long long* ei = (const long long*)ei_raw;
            s = (unsigned)ei[e];
            d = (unsigned)ei[(size_t)E + e];
        } else {
            const int* ei = (const int*)ei_raw;
            s = (unsigned)ei[e];
            d = (unsigned)ei[(size_t)E + e];
        }
        s = min(s, (unsigned)(N - 1));
        d = min(d, (unsigned)(N - 1));

        const uint4 ar = *(const uint4*)(g_AB + (size_t)s * 256 + gl * 8);
        const uint4 br = *(const uint4*)(g_AB + (size_t)d * 256 + 128 + gl * 8);
        const unsigned* au = (const unsigned*)&ar;
        const unsigned* bu = (const unsigned*)&br;

        float sum = 0.f;
#pragma unroll
        for (int i = 0; i < 4; ++i) {
            __half2 r = __hmax2(__hadd2(*(const __half2*)&au[i],
                                        *(const __half2*)&bu[i]), zero2);
            float2 f = __half22float2(r);
            sum = fmaf(f.x, wwf[2 * i],     sum);
            sum = fmaf(f.y, wwf[2 * i + 1], sum);
        }
#pragma unroll
        for (int off = 8; off; off >>= 1)
            sum += __shfl_xor_sync(0xFFFFFFFFu, sum, off);

        if (gl == 0)
            out[e] = sum + bias2;
    }
}

// ---------------------------------------------------------------------------
extern "C" void kernel_launch(void* const* d_in, const int* in_sizes, int n_in,
                              void* d_out, int out_size)
{
    const float* z   = (const float*)d_in[0];
    const void*  ei  = d_in[1];
    const float* W1  = (const float*)d_in[2];
    const float* b1  = (const float*)d_in[3];
    const float* W2  = (const float*)d_in[4];
    const float* b2  = (const float*)d_in[5];
    float*       out = (float*)d_out;

    const int N = in_sizes[0] / HID;   // 100000
    const int E = in_sizes[1] / 2;     // 1600000

    static int smem_set = 0;
    if (!smem_set) {
        cudaFuncSetAttribute(gemm_tc, cudaFuncAttributeMaxDynamicSharedMemorySize,
                             SMEM_BYTES);
        smem_set = 1;
    }

    prep_w<<<64, 512>>>(W1, (const int*)ei);

    const int nstrips = (N + 127) / 128;
    gemm_tc<<<148, 512, SMEM_BYTES>>>(z, b1, N, nstrips);

    const int edges_per_block = 8 * 2 * EDGE_ITER;   // 128
    edge_score<<<(E + edges_per_block - 1) / edges_per_block, 256>>>(
        ei, W2, b2, out, E, N);
}